// round 13
// baseline (speedup 1.0000x reference)
#include <cuda_runtime.h>

#define Bx 2048
#define Tt 512
#define Dd 6
#define Hh 40
#define Gg 160
#define BPC 14
#define GB 7              // batches per group (A: 0..6, B: 7..13)
#define NCTA 147          // 147*14 = 2058 >= 2048
#define THREADS 960       // slots: 3 layers x 80 gate-pairs x 4 k-quarters

#define ISTR 132          // IN stride: [x6|pad2|h0 40|h1 40|h2 40|spare4]
#define GSTR 162          // PART stride per batch
#define PQ (3*BPC*GSTR)   // PART stride per quarter  (6804)

// smem float offsets
#define INF 0
#define CF  (BPC*ISTR)               // 1848 : C[3][BPC][40]
#define PF  (CF + 3*BPC*Hh)          // 3528 : PART[4][3][BPC][GSTR]
#define WOF (PF + 4*PQ)              // 30744: Wout[40]
#define SMF (WOF + Hh + 8)           // 30792 floats = 123168 B

typedef unsigned long long u64;
#define LOG2E 1.4426950408889634f

__device__ __forceinline__ u64 pk(float a, float b) {
    u64 r; asm("mov.b64 %0, {%1, %2};" : "=l"(r) : "f"(a), "f"(b)); return r;
}
__device__ __forceinline__ u64 ffma2(u64 a, u64 b, u64 c) {
    u64 d; asm("fma.rn.f32x2 %0, %1, %2, %3;" : "=l"(d) : "l"(a), "l"(b), "l"(c)); return d;
}
__device__ __forceinline__ u64 add2(u64 a, u64 b) {
    u64 d; asm("add.rn.f32x2 %0, %1, %2;" : "=l"(d) : "l"(a), "l"(b)); return d;
}
__device__ __forceinline__ float ex2f(float x) {
    float y; asm("ex2.approx.f32 %0, %1;" : "=f"(y) : "f"(x)); return y;
}
__device__ __forceinline__ float rcpf(float x) {
    float y; asm("rcp.approx.f32 %0, %1;" : "=f"(y) : "f"(x)); return y;
}
__device__ __forceinline__ float sigf(float x)  { return rcpf(1.0f + ex2f(-LOG2E * x)); }
__device__ __forceinline__ float tanhf_(float x){ return fmaf(2.0f, rcpf(1.0f + ex2f(-2.0f*LOG2E*x)), -1.0f); }

__device__ __forceinline__ void sts64v(float* p, float a, float b) {
    asm volatile("st.shared.v2.f32 [%0], {%1, %2};"
                 :: "l"(__cvta_generic_to_shared(p)), "f"(a), "f"(b) : "memory");
}

// Accumulate 2 gates over NQ2 ulonglong2 k-loads (one k-quarter), GB batches.
template<int NQ2>
__device__ __forceinline__ void accumq(const u64* __restrict__ wa,
                                       const u64* __restrict__ wb,
                                       const float* __restrict__ inb,
                                       float* __restrict__ pout,
                                       float biasA, float biasB)
{
#pragma unroll
    for (int b = 0; b < GB; b++) {
        const ulonglong2* hp = (const ulonglong2*)(inb + b * ISTR);
        u64 a0 = 0, a1 = 0, c0 = 0, c1 = 0;
#pragma unroll
        for (int q = 0; q < NQ2; q++) {
            ulonglong2 v = hp[q];
            a0 = ffma2(wa[2*q],     v.x, a0);
            c0 = ffma2(wb[2*q],     v.x, c0);
            a1 = ffma2(wa[2*q + 1], v.y, a1);
            c1 = ffma2(wb[2*q + 1], v.y, c1);
        }
        a0 = add2(a0, a1); c0 = add2(c0, c1);
        float ua, va, ub, vb;
        asm("mov.b64 {%0, %1}, %2;" : "=f"(ua), "=f"(va) : "l"(a0));
        asm("mov.b64 {%0, %1}, %2;" : "=f"(ub), "=f"(vb) : "l"(c0));
        sts64v(pout + b * GSTR, ua + va + biasA, ub + vb + biasB);
    }
}

// Sum 4 quarter-partials, activations, write c and h for one unit-pair.
__device__ __forceinline__ void do_update(const float* p0, float* cp, float* hp)
{
    float gi0 = 0, gi1 = 0, gf0 = 0, gf1 = 0, gg0 = 0, gg1 = 0, go0 = 0, go1 = 0;
#pragma unroll
    for (int p = 0; p < 4; p++) {
        const float* pp = p0 + p * PQ;
        float2 A;
        A = *(const float2*)(pp);        gi0 += A.x; gi1 += A.y;
        A = *(const float2*)(pp + 40);   gf0 += A.x; gf1 += A.y;
        A = *(const float2*)(pp + 80);   gg0 += A.x; gg1 += A.y;
        A = *(const float2*)(pp + 120);  go0 += A.x; go1 += A.y;
    }
    float i0 = sigf(gi0),  i1 = sigf(gi1);
    float f0 = sigf(gf0),  f1 = sigf(gf1);
    float g0 = tanhf_(gg0), g1 = tanhf_(gg1);
    float o0 = sigf(go0),  o1 = sigf(go1);
    float2 c = *(const float2*)cp;
    float c0 = fmaf(f0, c.x, i0 * g0), c1 = fmaf(f1, c.y, i1 * g1);
    *(float2*)cp = make_float2(c0, c1);
    *(float2*)hp = make_float2(o0 * tanhf_(c0), o1 * tanhf_(c1));
}

extern __shared__ float smf[];

__global__ void __launch_bounds__(THREADS, 1)
lstm_fused_kernel(const float* __restrict__ x,
                  const float* __restrict__ Wih0, const float* __restrict__ Whh0,
                  const float* __restrict__ bih0, const float* __restrict__ bhh0,
                  const float* __restrict__ Wih1, const float* __restrict__ Whh1,
                  const float* __restrict__ bih1, const float* __restrict__ bhh1,
                  const float* __restrict__ Wih2, const float* __restrict__ Whh2,
                  const float* __restrict__ bih2, const float* __restrict__ bhh2,
                  const float* __restrict__ Wout, const float* __restrict__ bout,
                  float* __restrict__ out)
{
    const int tid  = threadIdx.x;
    const int w    = tid >> 5;
    const int lane = tid & 31;
    const int bglob = blockIdx.x * BPC;

    // zero IN + C; load Wout (PART written before read)
    for (int i = tid; i < PF; i += THREADS) smf[i] = 0.0f;
    if (tid < Hh) smf[WOF + tid] = Wout[tid];

    // ---- slot mapping: layer (10 warps each), k-quarter, gate pair ----
    const int layer = tid / 320;
    const int r0    = tid - layer * 320;
    const int qtr   = r0 / 80;
    const int lg    = 2 * (r0 - qtr * 80);        // even gate 0..158

    // ---- weights into registers (this gate pair, this k-quarter) ----
    u64 wa[10], wb[10];
    float biasA = 0.0f, biasB = 0.0f;
    {
        const int gA = lg, gB = lg + 1;
        if (layer == 0) {
            // virtual k (48): [x6|pad2|h0 40]; quarter = 12 floats = 6 pairs
            if (qtr == 0) {
#pragma unroll
                for (int i = 0; i < 3; i++) {
                    wa[i] = pk(Wih0[gA*6 + 2*i], Wih0[gA*6 + 2*i + 1]);
                    wb[i] = pk(Wih0[gB*6 + 2*i], Wih0[gB*6 + 2*i + 1]);
                }
                wa[3] = 0ULL; wb[3] = 0ULL;
#pragma unroll
                for (int i = 0; i < 2; i++) {
                    wa[4 + i] = pk(Whh0[gA*40 + 2*i], Whh0[gA*40 + 2*i + 1]);
                    wb[4 + i] = pk(Whh0[gB*40 + 2*i], Whh0[gB*40 + 2*i + 1]);
                }
                biasA = bih0[gA] + bhh0[gA];
                biasB = bih0[gB] + bhh0[gB];
            } else {
                // quarter q covers h0[12q-8 .. 12q+3]
                const int k0 = 12 * qtr - 8;
#pragma unroll
                for (int i = 0; i < 6; i++) {
                    wa[i] = pk(Whh0[gA*40 + k0 + 2*i], Whh0[gA*40 + k0 + 2*i + 1]);
                    wb[i] = pk(Whh0[gB*40 + k0 + 2*i], Whh0[gB*40 + k0 + 2*i + 1]);
                }
            }
#pragma unroll
            for (int i = 6; i < 10; i++) { wa[i] = 0ULL; wb[i] = 0ULL; }
        } else {
            // quarters 0,1: Wih over h(L-1) halves; 2,3: Whh over h(L) halves
            const float* wsrc = (layer == 1) ? ((qtr < 2) ? Wih1 : Whh1)
                                             : ((qtr < 2) ? Wih2 : Whh2);
            const int koff = (qtr & 1) * 20;
#pragma unroll
            for (int i = 0; i < 10; i++) {
                wa[i] = pk(wsrc[gA*40 + koff + 2*i], wsrc[gA*40 + koff + 2*i + 1]);
                wb[i] = pk(wsrc[gB*40 + koff + 2*i], wsrc[gB*40 + koff + 2*i + 1]);
            }
            if (qtr == 0) {
                biasA = (layer == 1) ? (bih1[gA] + bhh1[gA]) : (bih2[gA] + bhh2[gA]);
                biasB = (layer == 1) ? (bih1[gB] + bhh1[gB]) : (bih2[gB] + bhh2[gB]);
            }
        }
    }
    // input base for this slot's k-quarter
    const int ibase = (layer == 0) ? (qtr * 12)
                    : (layer == 1) ? (8  + (qtr < 2 ? qtr * 20 : 40 + (qtr - 2) * 20))
                                   : (48 + (qtr < 2 ? qtr * 20 : 40 + (qtr - 2) * 20));
    const float* const inbA = smf + INF + ibase;             // group A batches 0..6
    float* const poutA = smf + PF + qtr * PQ + layer * (BPC * GSTR) + lg;

    // ---- update slot (tid < 420, one per group) ----
    const bool uact = tid < 420;
    const int  sc   = uact ? tid : 0;
    const int  ul   = sc / 140;
    const int  ur   = sc - ul * 140;
    const int  ub   = ur / 20;
    const int  uu   = (ur - ub * 20) * 2;
    const int uoffP = PF + ul * (BPC * GSTR) + ub * GSTR + uu;
    const int uoffC = CF + (ul * BPC + ub) * Hh + uu;
    const int uoffH = INF + ub * ISTR + 8 + 40 * ul + uu;

    // ---- x staging: A: tid 0..41, B: tid 42..83 ----
    float xr = 0.0f;
    const float* xptr = 0;
    int xsm = 0;
    if (tid < 42) {
        int xb = tid / 6, xk = tid - xb * 6;
        int gb = bglob + xb; if (gb > Bx - 1) gb = Bx - 1;
        xptr = x + (size_t)gb * Tt * Dd + xk;
        xsm  = INF + xb * ISTR + xk;
    } else if (tid < 84) {
        int t2 = tid - 42;
        int xb = t2 / 6, xk = t2 - xb * 6;
        int gb = bglob + GB + xb; if (gb > Bx - 1) gb = Bx - 1;
        xptr = x + (size_t)gb * Tt * Dd + xk;
        xsm  = INF + (GB + xb) * ISTR + xk;
    }

    // ---- projection mapping (warp 0): 4 lanes per batch ----
    const int pb  = lane >> 2;
    const int sub = lane & 3;
    const int pbc = (pb < GB) ? pb : (GB - 1);
    const float boutv = bout[0];

    __syncthreads();

    // initial x staging
    if (tid < 42) { smf[xsm] = xptr[0]; xr = xptr[Dd]; }        // xr = x_A(1)
    else if (tid < 84) { xr = xptr[0]; }                         // xr = x_B(0)
    __syncthreads();

    for (int s = 0; s < Tt + 3; s++) {
        // ================= Phase 1: update(B,s-1) | accum(A,s) =============
        {
            int tu = s - 1 - ul;
            if (uact && tu >= 0 && tu < Tt)
                do_update(smf + uoffP + GB * GSTR,
                          smf + uoffC + GB * Hh,
                          smf + uoffH + GB * ISTR);
        }
        {
            int ta = s - layer;
            if (ta >= 0 && ta < Tt) {
                if (layer == 0) accumq<3>(wa, wb, inbA, poutA, biasA, biasB);
                else            accumq<5>(wa, wb, inbA, poutA, biasA, biasB);
            }
        }
        if (w == 0 && s >= 3) {        // proj(A, t=s-3)
            float ssum = 0.0f;
#pragma unroll
            for (int j = 0; j < 10; j++) {
                int u = sub * 10 + j;
                ssum = fmaf(smf[WOF + u], smf[INF + pbc * ISTR + 88 + u], ssum);
            }
            ssum += __shfl_down_sync(0xffffffffu, ssum, 2, 4);
            ssum += __shfl_down_sync(0xffffffffu, ssum, 1, 4);
            int gb = bglob + pb;
            if (sub == 0 && pb < GB && gb < Bx)
                out[(size_t)gb * Tt + (s - 3)] = ssum + boutv;
        }
        if (tid >= 42 && tid < 84) {   // stage x_B(s); prefetch x_B(s+1)
            smf[xsm] = xr;
            int tn = s + 1; if (tn > Tt - 1) tn = Tt - 1;
            xr = xptr[tn * Dd];
        }
        __syncthreads();

        // ================= Phase 2: update(A,s) | accum(B,s) ===============
        {
            int tu = s - ul;
            if (uact && tu >= 0 && tu < Tt)
                do_update(smf + uoffP, smf + uoffC, smf + uoffH);
        }
        {
            int ta = s - layer;
            if (ta >= 0 && ta < Tt) {
                if (layer == 0) accumq<3>(wa, wb, inbA + GB * ISTR, poutA + GB * GSTR, biasA, biasB);
                else            accumq<5>(wa, wb, inbA + GB * ISTR, poutA + GB * GSTR, biasA, biasB);
            }
        }
        if (w == 0 && s >= 3) {        // proj(B, t=s-3)
            float ssum = 0.0f;
#pragma unroll
            for (int j = 0; j < 10; j++) {
                int u = sub * 10 + j;
                ssum = fmaf(smf[WOF + u], smf[INF + (GB + pbc) * ISTR + 88 + u], ssum);
            }
            ssum += __shfl_down_sync(0xffffffffu, ssum, 2, 4);
            ssum += __shfl_down_sync(0xffffffffu, ssum, 1, 4);
            int gb = bglob + GB + pb;
            if (sub == 0 && pb < GB && gb < Bx)
                out[(size_t)gb * Tt + (s - 3)] = ssum + boutv;
        }
        if (tid < 42) {                // stage x_A(s+1); prefetch x_A(s+2)
            smf[xsm] = xr;
            int tn = s + 2; if (tn > Tt - 1) tn = Tt - 1;
            xr = xptr[tn * Dd];
        }
        __syncthreads();
    }
}

extern "C" void kernel_launch(void* const* d_in, const int* in_sizes, int n_in,
                              void* d_out, int out_size)
{
    (void)in_sizes; (void)n_in; (void)out_size;
    cudaFuncSetAttribute(lstm_fused_kernel,
                         cudaFuncAttributeMaxDynamicSharedMemorySize,
                         SMF * (int)sizeof(float));
    lstm_fused_kernel<<<NCTA, THREADS, SMF * sizeof(float)>>>(
        (const float*)d_in[0],
        (const float*)d_in[1],  (const float*)d_in[2],
        (const float*)d_in[3],  (const float*)d_in[4],
        (const float*)d_in[5],  (const float*)d_in[6],
        (const float*)d_in[7],  (const float*)d_in[8],
        (const float*)d_in[9],  (const float*)d_in[10],
        (const float*)d_in[11], (const float*)d_in[12],
        (const float*)d_in[13], (const float*)d_in[14],
        (float*)d_out);
}

// round 14
// speedup vs baseline: 1.1896x; 1.1896x over previous
#include <cuda_runtime.h>

#define Bx 2048
#define Tt 512
#define Dd 6
#define Hh 40
#define Gg 160
#define BPC 14
#define GB 7              // batches per group (A: 0..6, B: 7..13)
#define NCTA 147          // 147*14 = 2058 >= 2048
#define THREADS 480       // slots: 3 layers x 80 gate-pairs x 2 k-halves

#define ISTR 132          // IN stride: [x6|pad2|h0 40|h1 40|h2 40|spare4]
#define GSTR 162          // PART stride per batch
#define PHALF (3*BPC*GSTR)

// smem float offsets
#define INF 0
#define CF  (BPC*ISTR)               // C[3][BPC][40]
#define PF  (CF + 3*BPC*Hh)          // PART[2][3][BPC][GSTR]
#define WOF (PF + 2*PHALF)           // Wout[40]
#define SMF (WOF + Hh + 8)

typedef unsigned long long u64;
#define LOG2E 1.4426950408889634f

__device__ __forceinline__ u64 pk(float a, float b) {
    u64 r; asm("mov.b64 %0, {%1, %2};" : "=l"(r) : "f"(a), "f"(b)); return r;
}
__device__ __forceinline__ u64 ffma2(u64 a, u64 b, u64 c) {
    u64 d; asm("fma.rn.f32x2 %0, %1, %2, %3;" : "=l"(d) : "l"(a), "l"(b), "l"(c)); return d;
}
__device__ __forceinline__ u64 add2(u64 a, u64 b) {
    u64 d; asm("add.rn.f32x2 %0, %1, %2;" : "=l"(d) : "l"(a), "l"(b)); return d;
}
__device__ __forceinline__ float ex2f(float x) {
    float y; asm("ex2.approx.f32 %0, %1;" : "=f"(y) : "f"(x)); return y;
}
__device__ __forceinline__ float rcpf(float x) {
    float y; asm("rcp.approx.f32 %0, %1;" : "=f"(y) : "f"(x)); return y;
}
__device__ __forceinline__ float sigf(float x)  { return rcpf(1.0f + ex2f(-LOG2E * x)); }
__device__ __forceinline__ float tanhf_(float x){ return fmaf(2.0f, rcpf(1.0f + ex2f(-2.0f*LOG2E*x)), -1.0f); }

__device__ __forceinline__ void sts64v(float* p, float a, float b) {
    asm volatile("st.shared.v2.f32 [%0], {%1, %2};"
                 :: "l"(__cvta_generic_to_shared(p)), "f"(a), "f"(b) : "memory");
}

// Accumulate 2 gates (A,B) over NU u64 k-pairs (one k-half) for GB batches.
template<int NU>
__device__ __forceinline__ void accum2g(const u64* __restrict__ wa,
                                        const u64* __restrict__ wb,
                                        const float* __restrict__ inb,
                                        float* __restrict__ pout,
                                        float biasA, float biasB)
{
#pragma unroll 2
    for (int b = 0; b < GB; b++) {
        const ulonglong2* hp = (const ulonglong2*)(inb + b * ISTR);
        u64 a0 = 0, a1 = 0, c0 = 0, c1 = 0;
#pragma unroll
        for (int q = 0; q < NU / 2; q++) {
            ulonglong2 v = hp[q];
            a0 = ffma2(wa[2*q],     v.x, a0);
            c0 = ffma2(wb[2*q],     v.x, c0);
            a1 = ffma2(wa[2*q + 1], v.y, a1);
            c1 = ffma2(wb[2*q + 1], v.y, c1);
        }
        a0 = add2(a0, a1); c0 = add2(c0, c1);
        float ua, va, ub, vb;
        asm("mov.b64 {%0, %1}, %2;" : "=f"(ua), "=f"(va) : "l"(a0));
        asm("mov.b64 {%0, %1}, %2;" : "=f"(ub), "=f"(vb) : "l"(c0));
        sts64v(pout + b * GSTR, ua + va + biasA, ub + vb + biasB);
    }
}

// Sum partial halves, activations, write c and h for one unit-pair.
__device__ __forceinline__ void do_update(const float* p0, float* cp, float* hp)
{
    const float* p1 = p0 + PHALF;
    float2 A, B;
    A = *(const float2*)(p0);        B = *(const float2*)(p1);
    float i0 = sigf(A.x + B.x),  i1 = sigf(A.y + B.y);
    A = *(const float2*)(p0 + 40);   B = *(const float2*)(p1 + 40);
    float f0 = sigf(A.x + B.x),  f1 = sigf(A.y + B.y);
    A = *(const float2*)(p0 + 80);   B = *(const float2*)(p1 + 80);
    float g0 = tanhf_(A.x + B.x), g1 = tanhf_(A.y + B.y);
    A = *(const float2*)(p0 + 120);  B = *(const float2*)(p1 + 120);
    float o0 = sigf(A.x + B.x),  o1 = sigf(A.y + B.y);
    float2 c = *(const float2*)cp;
    float c0 = fmaf(f0, c.x, i0 * g0), c1 = fmaf(f1, c.y, i1 * g1);
    *(float2*)cp = make_float2(c0, c1);
    *(float2*)hp = make_float2(o0 * tanhf_(c0), o1 * tanhf_(c1));
}

extern __shared__ float smf[];

__global__ void __launch_bounds__(THREADS, 1)
lstm_fused_kernel(const float* __restrict__ x,
                  const float* __restrict__ Wih0, const float* __restrict__ Whh0,
                  const float* __restrict__ bih0, const float* __restrict__ bhh0,
                  const float* __restrict__ Wih1, const float* __restrict__ Whh1,
                  const float* __restrict__ bih1, const float* __restrict__ bhh1,
                  const float* __restrict__ Wih2, const float* __restrict__ Whh2,
                  const float* __restrict__ bih2, const float* __restrict__ bhh2,
                  const float* __restrict__ Wout, const float* __restrict__ bout,
                  float* __restrict__ out)
{
    const int tid  = threadIdx.x;
    const int w    = tid >> 5;
    const int lane = tid & 31;
    const int bglob = blockIdx.x * BPC;
    const bool updFirst = (w & 1);     // stagger: odd warps update->accum

    // zero IN + C + PART; load Wout
    for (int i = tid; i < PF; i += THREADS) smf[i] = 0.0f;
    if (tid < Hh) smf[WOF + tid] = Wout[tid];

    // ---- slot mapping: layer (5 warps each), k-half, gate pair ----
    const int layer = tid / 160;
    const int idx2  = tid - layer * 160;
    const int half  = (idx2 >= 80) ? 1 : 0;
    const int lg    = 2 * (idx2 - half * 80);     // even gate 0..158

    // ---- weights into registers (this gate pair, this k-half) ----
    u64 wa[20], wb[20];
    float biasA = 0.0f, biasB = 0.0f;
    {
        const int gA = lg, gB = lg + 1;
        if (layer == 0) {
            if (half == 0) {
                // virtual k 0..23: [x(6) | pad(2) | h0[0..15]]
#pragma unroll
                for (int i = 0; i < 3; i++) {
                    wa[i] = pk(Wih0[gA*6 + 2*i], Wih0[gA*6 + 2*i + 1]);
                    wb[i] = pk(Wih0[gB*6 + 2*i], Wih0[gB*6 + 2*i + 1]);
                }
                wa[3] = 0ULL; wb[3] = 0ULL;
#pragma unroll
                for (int i = 0; i < 8; i++) {
                    wa[4 + i] = pk(Whh0[gA*40 + 2*i], Whh0[gA*40 + 2*i + 1]);
                    wb[4 + i] = pk(Whh0[gB*40 + 2*i], Whh0[gB*40 + 2*i + 1]);
                }
                biasA = bih0[gA] + bhh0[gA];
                biasB = bih0[gB] + bhh0[gB];
            } else {
                // virtual k 24..47 -> h0[16..39]
#pragma unroll
                for (int i = 0; i < 12; i++) {
                    wa[i] = pk(Whh0[gA*40 + 16 + 2*i], Whh0[gA*40 + 17 + 2*i]);
                    wb[i] = pk(Whh0[gB*40 + 16 + 2*i], Whh0[gB*40 + 17 + 2*i]);
                }
            }
#pragma unroll
            for (int i = 12; i < 20; i++) { wa[i] = 0ULL; wb[i] = 0ULL; }
        } else {
            const float* wsrc = (layer == 1) ? (half ? Whh1 : Wih1)
                                             : (half ? Whh2 : Wih2);
#pragma unroll
            for (int i = 0; i < 20; i++) {
                wa[i] = pk(wsrc[gA*40 + 2*i], wsrc[gA*40 + 2*i + 1]);
                wb[i] = pk(wsrc[gB*40 + 2*i], wsrc[gB*40 + 2*i + 1]);
            }
            if (half == 0) {
                biasA = (layer == 1) ? (bih1[gA] + bhh1[gA]) : (bih2[gA] + bhh2[gA]);
                biasB = (layer == 1) ? (bih1[gB] + bhh1[gB]) : (bih2[gB] + bhh2[gB]);
            }
        }
    }
    const int ibase = (layer == 0) ? (half * 24)
                    : (layer == 1) ? (8 + half * 40)
                                   : (48 + half * 40);
    const float* const inbA = smf + INF + ibase;             // group A batches 0..6
    const float* const inbB = inbA + GB * ISTR;              // group B batches 7..13
    float* const poutA = smf + PF + half * PHALF + layer * (BPC * GSTR) + lg;
    float* const poutB = poutA + GB * GSTR;

    // ---- update slot (1 per thread, 420 total per group) ----
    const bool uact = tid < 420;
    const int  sc   = uact ? tid : 0;
    const int  ul   = sc / 140;
    const int  ur   = sc - ul * 140;
    const int  ub   = ur / 20;
    const int  uu   = (ur - ub * 20) * 2;
    const int uoffP = PF + ul * (BPC * GSTR) + ub * GSTR + uu;
    const int uoffC = CF + (ul * BPC + ub) * Hh + uu;
    const int uoffH = INF + ub * ISTR + 8 + 40 * ul + uu;

    // ---- x staging ----
    float xr = 0.0f;
    const float* xptr = 0;
    int xsm = 0;
    if (tid < 42) {
        int xb = tid / 6, xk = tid - xb * 6;
        int gb = bglob + xb; if (gb > Bx - 1) gb = Bx - 1;
        xptr = x + (size_t)gb * Tt * Dd + xk;
        xsm  = INF + xb * ISTR + xk;
    } else if (tid < 84) {
        int t2 = tid - 42;
        int xb = t2 / 6, xk = t2 - xb * 6;
        int gb = bglob + GB + xb; if (gb > Bx - 1) gb = Bx - 1;
        xptr = x + (size_t)gb * Tt * Dd + xk;
        xsm  = INF + (GB + xb) * ISTR + xk;
    }

    // ---- projection mapping (warp 0): 4 lanes per batch ----
    const int pb  = lane >> 2;                 // 0..7
    const int sub = lane & 3;
    const int pbc = (pb < GB) ? pb : (GB - 1);
    const float boutv = bout[0];

    __syncthreads();

    // initial x staging: x_A(0) into smem; prefetch x_A(1) / x_B(0)
    if (tid < 42) { smf[xsm] = xptr[0]; xr = xptr[Dd]; }       // xr = x_A(1)
    else if (tid < 84) { xr = xptr[0]; }                        // xr = x_B(0)
    __syncthreads();

    for (int s = 0; s < Tt + 3; s++) {
        // ===== Phase 1: update(B,s-1) | accum(A,s) — warp-parity staggered =====
        {
            const int tu = s - 1 - ul;
            const bool doU = uact && tu >= 0 && tu < Tt;
            const int ta = s - layer;
            const bool doA = ta >= 0 && ta < Tt;

            if (updFirst && doU)
                do_update(smf + uoffP + GB * GSTR, smf + uoffC + GB * Hh,
                          smf + uoffH + GB * ISTR);
            if (doA) {
                if (layer == 0) accum2g<12>(wa, wb, inbA, poutA, biasA, biasB);
                else            accum2g<20>(wa, wb, inbA, poutA, biasA, biasB);
            }
            if (!updFirst && doU)
                do_update(smf + uoffP + GB * GSTR, smf + uoffC + GB * Hh,
                          smf + uoffH + GB * ISTR);
        }
        if (w == 0 && s >= 3) {        // proj(A, t=s-3): h2_A holds h2(s-3) here
            float ssum = 0.0f;
#pragma unroll
            for (int j = 0; j < 10; j++) {
                int u = sub * 10 + j;
                ssum = fmaf(smf[WOF + u], smf[INF + pbc * ISTR + 88 + u], ssum);
            }
            ssum += __shfl_down_sync(0xffffffffu, ssum, 2, 4);
            ssum += __shfl_down_sync(0xffffffffu, ssum, 1, 4);
            int gb = bglob + pb;
            if (sub == 0 && pb < GB && gb < Bx)
                out[(size_t)gb * Tt + (s - 3)] = ssum + boutv;
        }
        if (tid >= 42 && tid < 84) {   // stage x_B(s); prefetch x_B(s+1)
            smf[xsm] = xr;
            int tn = s + 1; if (tn > Tt - 1) tn = Tt - 1;
            xr = xptr[tn * Dd];
        }
        __syncthreads();

        // ===== Phase 2: update(A,s) | accum(B,s) — warp-parity staggered =====
        {
            const int tu = s - ul;
            const bool doU = uact && tu >= 0 && tu < Tt;
            const int ta = s - layer;
            const bool doB = ta >= 0 && ta < Tt;

            if (updFirst && doU)
                do_update(smf + uoffP, smf + uoffC, smf + uoffH);
            if (doB) {
                if (layer == 0) accum2g<12>(wa, wb, inbB, poutB, biasA, biasB);
                else            accum2g<20>(wa, wb, inbB, poutB, biasA, biasB);
            }
            if (!updFirst && doU)
                do_update(smf + uoffP, smf + uoffC, smf + uoffH);
        }
        if (w == 0 && s >= 3) {        // proj(B, t=s-3)
            float ssum = 0.0f;
#pragma unroll
            for (int j = 0; j < 10; j++) {
                int u = sub * 10 + j;
                ssum = fmaf(smf[WOF + u], smf[INF + (GB + pbc) * ISTR + 88 + u], ssum);
            }
            ssum += __shfl_down_sync(0xffffffffu, ssum, 2, 4);
            ssum += __shfl_down_sync(0xffffffffu, ssum, 1, 4);
            int gb = bglob + GB + pb;
            if (sub == 0 && pb < GB && gb < Bx)
                out[(size_t)gb * Tt + (s - 3)] = ssum + boutv;
        }
        if (tid < 42) {                // stage x_A(s+1); prefetch x_A(s+2)
            smf[xsm] = xr;
            int tn = s + 2; if (tn > Tt - 1) tn = Tt - 1;
            xr = xptr[tn * Dd];
        }
        __syncthreads();
    }
}

extern "C" void kernel_launch(void* const* d_in, const int* in_sizes, int n_in,
                              void* d_out, int out_size)
{
    (void)in_sizes; (void)n_in; (void)out_size;
    cudaFuncSetAttribute(lstm_fused_kernel,
                         cudaFuncAttributeMaxDynamicSharedMemorySize,
                         SMF * (int)sizeof(float));
    lstm_fused_kernel<<<NCTA, THREADS, SMF * sizeof(float)>>>(
        (const float*)d_in[0],
        (const float*)d_in[1],  (const float*)d_in[2],
        (const float*)d_in[3],  (const float*)d_in[4],
        (const float*)d_in[5],  (const float*)d_in[6],
        (const float*)d_in[7],  (const float*)d_in[8],
        (const float*)d_in[9],  (const float*)d_in[10],
        (const float*)d_in[11], (const float*)d_in[12],
        (const float*)d_in[13], (const float*)d_in[14],
        (float*)d_out);
}

// round 17
// speedup vs baseline: 1.2563x; 1.0561x over previous
#include <cuda_runtime.h>

#define Bx 2048
#define Tt 512
#define Dd 6
#define Hh 40
#define BPC 14
#define NCTA 147          // 147*14 = 2058 >= 2048
#define THREADS 480       // slots: 3 layers x 40 units x 4 k-quarters

#define ISTR 132          // IN stride: [x6|pad2|h0 40|h1 40|h2 40|spare4]
#define USTR 164          // PART batch stride (40 units x 4 gates + pad)
#define LSTRP (BPC*USTR)  // PART layer stride (2296)
#define PQ (3*LSTRP)      // PART quarter stride (6888)

// smem float offsets (dynamic)
#define INF 0
#define CF  (BPC*ISTR)               //  1848 : C[3][BPC][40]
#define PF  (CF + 3*BPC*Hh)          //  3528 : PART[4][3][BPC][40][4]
#define WOF (PF + 4*PQ)              // 31080 : Wout[40]
#define SMF (WOF + Hh + 4)           // 31124 floats = 124496 B

#define NUNITS (3*BPC*Hh)            // 1680 update slots

typedef unsigned long long u64;
#define LOG2E 1.4426950408889634f

__device__ __forceinline__ u64 pk(float a, float b) {
    u64 r; asm("mov.b64 %0, {%1, %2};" : "=l"(r) : "f"(a), "f"(b)); return r;
}
__device__ __forceinline__ u64 ffma2(u64 a, u64 b, u64 c) {
    u64 d; asm("fma.rn.f32x2 %0, %1, %2, %3;" : "=l"(d) : "l"(a), "l"(b), "l"(c)); return d;
}
__device__ __forceinline__ float ex2f(float x) {
    float y; asm("ex2.approx.f32 %0, %1;" : "=f"(y) : "f"(x)); return y;
}
__device__ __forceinline__ float rcpf(float x) {
    float y; asm("rcp.approx.f32 %0, %1;" : "=f"(y) : "f"(x)); return y;
}
__device__ __forceinline__ float sigf(float x)  { return rcpf(1.0f + ex2f(-LOG2E * x)); }
__device__ __forceinline__ float tanhf_(float x){ return fmaf(2.0f, rcpf(1.0f + ex2f(-2.0f*LOG2E*x)), -1.0f); }

__device__ __forceinline__ u64 lds64(const float* p) {
    u64 v;
    asm volatile("ld.shared.b64 %0, [%1];" : "=l"(v) : "l"(__cvta_generic_to_shared(p)));
    return v;
}
__device__ __forceinline__ void sts128(float* p, float a, float b, float c, float d) {
    asm volatile("st.shared.v4.f32 [%0], {%1, %2, %3, %4};"
                 :: "l"(__cvta_generic_to_shared(p)), "f"(a), "f"(b), "f"(c), "f"(d) : "memory");
}
__device__ __forceinline__ float hsum2(u64 v) {
    float a, b; asm("mov.b64 {%0, %1}, %2;" : "=f"(a), "=f"(b) : "l"(v));
    return a + b;
}

// Accumulate 4 gate rows (i,f,g,o) of one unit over NU u64 k-pairs (one
// k-quarter) for all BPC batches. One 8B broadcast load feeds 4 FFMA2.
template<int NU>
__device__ __forceinline__ void accum4(const u64* __restrict__ wi,
                                       const u64* __restrict__ wf,
                                       const u64* __restrict__ wg,
                                       const u64* __restrict__ wo,
                                       const float* __restrict__ inb,
                                       float* __restrict__ pout,
                                       float bi, float bf, float bg, float bo)
{
#pragma unroll 2
    for (int b = 0; b < BPC; b++) {
        const float* hp = inb + b * ISTR;
        u64 ai = 0, af = 0, ag = 0, ao = 0;
#pragma unroll
        for (int q = 0; q < NU; q++) {
            u64 v = lds64(hp + 2 * q);
            ai = ffma2(wi[q], v, ai);
            af = ffma2(wf[q], v, af);
            ag = ffma2(wg[q], v, ag);
            ao = ffma2(wo[q], v, ao);
        }
        sts128(pout + b * USTR,
               hsum2(ai) + bi, hsum2(af) + bf, hsum2(ag) + bg, hsum2(ao) + bo);
    }
}

extern __shared__ float smf[];

__global__ void __launch_bounds__(THREADS, 1)
lstm_fused_kernel(const float* __restrict__ x,
                  const float* __restrict__ Wih0, const float* __restrict__ Whh0,
                  const float* __restrict__ bih0, const float* __restrict__ bhh0,
                  const float* __restrict__ Wih1, const float* __restrict__ Whh1,
                  const float* __restrict__ bih1, const float* __restrict__ bhh1,
                  const float* __restrict__ Wih2, const float* __restrict__ Whh2,
                  const float* __restrict__ bih2, const float* __restrict__ bhh2,
                  const float* __restrict__ Wout, const float* __restrict__ bout,
                  float* __restrict__ out)
{
    const int tid  = threadIdx.x;
    const int bglob = blockIdx.x * BPC;

    // zero IN + C; load Wout (PART written before read)
    for (int i = tid; i < PF; i += THREADS) smf[i] = 0.0f;
    if (tid < Hh) smf[WOF + tid] = Wout[tid];

    // ---- slot mapping: (layer, k-quarter, unit) ----
    const int layer = tid / 160;
    const int r0    = tid - layer * 160;
    const int qtr   = r0 / 40;
    const int u     = r0 - qtr * 40;       // unit 0..39

    // ---- weights into registers: 4 gate rows x one k-quarter ----
    u64 wi[10], wf_[10], wg[10], wo[10];
    float bi = 0.f, bf = 0.f, bg = 0.f, bo = 0.f;
    {
        const int gi = u, gf = 40 + u, gg = 80 + u, go = 120 + u;
        if (layer == 0) {
            // virtual k (48 floats): [x6|pad2|h0 40]; quarter = 12 floats = 6 pairs
            if (qtr == 0) {
#pragma unroll
                for (int i = 0; i < 3; i++) {
                    wi[i]  = pk(Wih0[gi*6 + 2*i], Wih0[gi*6 + 2*i + 1]);
                    wf_[i] = pk(Wih0[gf*6 + 2*i], Wih0[gf*6 + 2*i + 1]);
                    wg[i]  = pk(Wih0[gg*6 + 2*i], Wih0[gg*6 + 2*i + 1]);
                    wo[i]  = pk(Wih0[go*6 + 2*i], Wih0[go*6 + 2*i + 1]);
                }
                wi[3] = 0ULL; wf_[3] = 0ULL; wg[3] = 0ULL; wo[3] = 0ULL;
#pragma unroll
                for (int i = 0; i < 2; i++) {
                    wi[4+i]  = pk(Whh0[gi*40 + 2*i], Whh0[gi*40 + 2*i + 1]);
                    wf_[4+i] = pk(Whh0[gf*40 + 2*i], Whh0[gf*40 + 2*i + 1]);
                    wg[4+i]  = pk(Whh0[gg*40 + 2*i], Whh0[gg*40 + 2*i + 1]);
                    wo[4+i]  = pk(Whh0[go*40 + 2*i], Whh0[go*40 + 2*i + 1]);
                }
                bi = bih0[gi] + bhh0[gi];  bf = bih0[gf] + bhh0[gf];
                bg = bih0[gg] + bhh0[gg];  bo = bih0[go] + bhh0[go];
            } else {
                // quarter q covers h0[12q-8 .. 12q+3]
                const int k0 = 12 * qtr - 8;
#pragma unroll
                for (int i = 0; i < 6; i++) {
                    wi[i]  = pk(Whh0[gi*40 + k0 + 2*i], Whh0[gi*40 + k0 + 2*i + 1]);
                    wf_[i] = pk(Whh0[gf*40 + k0 + 2*i], Whh0[gf*40 + k0 + 2*i + 1]);
                    wg[i]  = pk(Whh0[gg*40 + k0 + 2*i], Whh0[gg*40 + k0 + 2*i + 1]);
                    wo[i]  = pk(Whh0[go*40 + k0 + 2*i], Whh0[go*40 + k0 + 2*i + 1]);
                }
            }
#pragma unroll
            for (int i = 6; i < 10; i++) { wi[i] = 0ULL; wf_[i] = 0ULL; wg[i] = 0ULL; wo[i] = 0ULL; }
        } else {
            // quarters 0,1: Wih over h_{l-1} halves; 2,3: Whh over h_l halves
            const float* ws = (layer == 1) ? ((qtr < 2) ? Wih1 : Whh1)
                                           : ((qtr < 2) ? Wih2 : Whh2);
            const int koff = (qtr & 1) * 20;
#pragma unroll
            for (int i = 0; i < 10; i++) {
                wi[i]  = pk(ws[gi*40 + koff + 2*i], ws[gi*40 + koff + 2*i + 1]);
                wf_[i] = pk(ws[gf*40 + koff + 2*i], ws[gf*40 + koff + 2*i + 1]);
                wg[i]  = pk(ws[gg*40 + koff + 2*i], ws[gg*40 + koff + 2*i + 1]);
                wo[i]  = pk(ws[go*40 + koff + 2*i], ws[go*40 + koff + 2*i + 1]);
            }
            if (qtr == 0) {
                const float* b1 = (layer == 1) ? bih1 : bih2;
                const float* b2 = (layer == 1) ? bhh1 : bhh2;
                bi = b1[gi] + b2[gi];  bf = b1[gf] + b2[gf];
                bg = b1[gg] + b2[gg];  bo = b1[go] + b2[go];
            }
        }
    }
    // input base for this slot's k-quarter
    const int ibase = (layer == 0) ? (qtr * 12)
                    : (layer == 1) ? (8  + (qtr < 2 ? qtr * 20 : 40 + (qtr - 2) * 20))
                                   : (48 + (qtr < 2 ? qtr * 20 : 40 + (qtr - 2) * 20));
    const float* const inb = smf + INF + ibase;
    float* const pout = smf + PF + qtr * PQ + layer * LSTRP + u * 4;

    // ---- update slots: 1680 single-unit slots over 480 threads (4 each) ----
    int upP[4], upC[4], upH[4], uplay[4]; bool upact[4];
#pragma unroll
    for (int j = 0; j < 4; j++) {
        int si = tid + THREADS * j;
        upact[j] = si < NUNITS;                // 1680
        int sc = upact[j] ? si : 0;
        int l = sc / (BPC * Hh), r = sc - l * (BPC * Hh), b = r / Hh, uu = r - b * Hh;
        uplay[j] = l;
        upP[j] = PF + l * LSTRP + b * USTR + uu * 4;
        upC[j] = CF + (l * BPC + b) * Hh + uu;
        upH[j] = INF + b * ISTR + 8 + 40 * l + uu;
    }

    // ---- x staging: threads 0..83 own (b,k) ----
    const int xb = tid / Dd, xk = tid - (tid / Dd) * Dd;
    int gbx = bglob + xb; if (gbx > Bx - 1) gbx = Bx - 1;
    const float* const xptr = x + (size_t)gbx * Tt * Dd + xk;
    float xr = 0.0f;
    if (tid < BPC * Dd) {
        smf[INF + xb * ISTR + xk] = xptr[0];   // x(0)
        xr = xptr[Dd];                          // x(1)
    }

    // ---- projection mapping: tid<64, 4 lanes per batch, 14 batches ----
    const int pb  = tid >> 2;                  // 0..15 (tid<64)
    const int sub = tid & 3;
    const int pbc = (pb < BPC) ? pb : 0;
    int gbp = bglob + pb; if (gbp > Bx - 1) gbp = Bx - 1;
    const float boutv = bout[0];

    __syncthreads();

    for (int s = 0; s < Tt + 3; s++) {
        // ============== accum phase (all layers/quarters concurrent) ======
        {
            int ta = s - layer;
            if (ta >= 0 && ta < Tt) {
                if (layer == 0)
                    accum4<6>(wi, wf_, wg, wo, inb, pout, bi, bf, bg, bo);
                else
                    accum4<10>(wi, wf_, wg, wo, inb, pout, bi, bf, bg, bo);
            }
        }
        // projection of t=s-3 (tid<64; h2(s-3) stable during accum)
        if (tid < 64 && s >= 3) {
            float ssum = 0.0f;
#pragma unroll
            for (int j = 0; j < 10; j++) {
                int uu = sub * 10 + j;
                ssum = fmaf(smf[WOF + uu], smf[INF + pbc * ISTR + 88 + uu], ssum);
            }
            ssum += __shfl_down_sync(0xffffffffu, ssum, 2, 4);
            ssum += __shfl_down_sync(0xffffffffu, ssum, 1, 4);
            if (sub == 0 && pb < BPC && bglob + pb < Bx)
                out[(size_t)gbp * Tt + (s - 3)] = ssum + boutv;
        }
        __syncthreads();

        // ============== update phase (sum 4 quarter-partials) =============
#pragma unroll
        for (int j = 0; j < 4; j++) {
            int tu = s - uplay[j];
            if (upact[j] && tu >= 0 && tu < Tt) {
                const float* p = smf + upP[j];
                float4 P0 = *(const float4*)(p);
                float4 P1 = *(const float4*)(p + PQ);
                float4 P2 = *(const float4*)(p + 2 * PQ);
                float4 P3 = *(const float4*)(p + 3 * PQ);
                float iv = sigf(P0.x + P1.x + P2.x + P3.x);
                float fv = sigf(P0.y + P1.y + P2.y + P3.y);
                float gv = tanhf_(P0.z + P1.z + P2.z + P3.z);
                float ov = sigf(P0.w + P1.w + P2.w + P3.w);
                float c = smf[upC[j]];
                c = fmaf(fv, c, iv * gv);
                smf[upC[j]] = c;
                smf[upH[j]] = ov * tanhf_(c);
            }
        }
        // stage x(s+1), prefetch x(s+2)
        if (tid < BPC * Dd) {
            smf[INF + xb * ISTR + xk] = xr;
            int tn = s + 2; if (tn > Tt - 1) tn = Tt - 1;
            xr = xptr[tn * Dd];
        }
        __syncthreads();
    }
}

extern "C" void kernel_launch(void* const* d_in, const int* in_sizes, int n_in,
                              void* d_out, int out_size)
{
    (void)in_sizes; (void)n_in; (void)out_size;
    cudaFuncSetAttribute(lstm_fused_kernel,
                         cudaFuncAttributeMaxDynamicSharedMemorySize,
                         SMF * (int)sizeof(float));
    lstm_fused_kernel<<<NCTA, THREADS, SMF * sizeof(float)>>>(
        (const float*)d_in[0],
        (const float*)d_in[1],  (const float*)d_in[2],
        (const float*)d_in[3],  (const float*)d_in[4],
        (const float*)d_in[5],  (const float*)d_in[6],
        (const float*)d_in[7],  (const float*)d_in[8],
        (const float*)d_in[9],  (const float*)d_in[10],
        (const float*)d_in[11], (const float*)d_in[12],
        (const float*)d_in[13], (const float*)d_in[14],
        (float*)d_out);
}